// round 5
// baseline (speedup 1.0000x reference)
#include <cuda_runtime.h>
#include <math.h>

#define BB 8
#define PP 16
#define VV 32
#define DD 686
#define N_PC 16384
#define N_NS 8192
#define N_OD 8192
#define PD (PP*DD)          /* 10976 */

/* Output layout: tuple members flattened & concatenated in order */
#define OFF_OVERLAP 0
#define OFF_DIST    2048
#define OFF_X       2099200
#define OFF_SURFD   2362624
#define OFF_SURFP   3767552
#define OFF_NS      4030976
#define OFF_OUTD    5079552

__device__ float g_dirs[DD*3];
__device__ float g_lv[BB*PP*VV*3];
__device__ float g_mean[BB*PP*3];
__device__ float g_scale[BB*PP];
__device__ float g_norm[BB*PP*DD*3];

__device__ __forceinline__ float fex2(float x){ float y; asm("ex2.approx.f32 %0, %1;" : "=f"(y) : "f"(x)); return y; }
__device__ __forceinline__ float flg2(float x){ float y; asm("lg2.approx.f32 %0, %1;" : "=f"(y) : "f"(x)); return y; }
__device__ __forceinline__ float frcp(float x){ float y; asm("rcp.approx.f32 %0, %1;" : "=f"(y) : "f"(x)); return y; }
__device__ __forceinline__ float frsq(float x){ float y; asm("rsqrt.approx.f32 %0, %1;" : "=f"(y) : "f"(x)); return y; }

/* h_out = (sum_v clip(max(z_v,0)/maxz)^pe)^(1/pe) * maxz */
__device__ __forceinline__ float support_hout(const float* __restrict__ sv,
                                              float dx, float dy, float dz,
                                              float pe, float inv_pe)
{
    float z[VV];
    float zmax = -1e30f;
#pragma unroll
    for (int v = 0; v < VV; v++) {
        float zz = fmaf(sv[3*v+2], dz, fmaf(sv[3*v+1], dy, sv[3*v]*dx));
        z[v] = zz;
        zmax = fmaxf(zmax, zz);
    }
    float maxz = fminf(fmaxf(zmax, 1e-30f), 1e30f);
    float k = frcp(maxz);
    float sum = 0.f;
#pragma unroll
    for (int v = 0; v < VV; v++) {
        float t = fmaxf(z[v], 0.f) * k;       /* lg2(0) = -inf -> ex2 = 0: exact zero contribution */
        sum += fex2(pe * flg2(t));
    }
    float h = fex2(inv_pe * flg2(sum));
    return h * maxz;
}

/* ---------------- kernel 0: directions (match numpy float64 path) ---------- */
__global__ void k_dirs()
{
    int t = threadIdx.x;
    if (t >= DD) return;
    const double PI = 3.14159265358979323846;
    int i, j;
    if (t < 684) { i = 1 + t/38; j = t % 38; }
    else if (t == 684) { i = 0;  j = 0; }
    else               { i = 19; j = 0; }
    double th1 = (i == 19) ? (PI*0.5) : (-PI*0.5 + (PI/19.0)*(double)i);
    double th2 = -PI + (PI/19.0)*(double)j;
    double c1 = cos(th1), s1 = sin(th1), c2 = cos(th2), s2 = sin(th2);
    g_dirs[t*3+0] = (float)(c1*c2);
    g_dirs[t*3+1] = (float)(c1*s2);
    g_dirs[t*3+2] = (float)(s1);
}

/* -------- kernel 1: mean, local verts, scale (max support over DIRS), x ---- */
__global__ void k_prep(const float* __restrict__ verts,
                       const float* __restrict__ smooth,
                       float* __restrict__ out)
{
    __shared__ float sv[VV*3];
    __shared__ float smean[3];
    __shared__ float red[128];
    int bp = blockIdx.x;
    int t = threadIdx.x;
    if (t < VV*3) sv[t] = verts[bp*VV*3 + t];
    __syncthreads();
    if (t < 3) {
        float s = 0.f;
        for (int v = 0; v < VV; v++) s += sv[3*v + t];
        smean[t] = s * (1.0f/32.0f);
    }
    __syncthreads();
    if (t < VV*3) {
        float lvv = sv[t] - smean[t % 3];
        sv[t] = lvv;
        g_lv[bp*VV*3 + t] = lvv;
    }
    if (t < 3) g_mean[bp*3 + t] = smean[t];
    __syncthreads();

    float pe = smooth[bp], inv_pe = 1.0f/pe;
    float m = -1e30f;
    for (int d = t; d < DD; d += blockDim.x) {
        float dx = g_dirs[3*d], dy = g_dirs[3*d+1], dz = g_dirs[3*d+2];
        float h = support_hout(sv, dx, dy, dz, pe, inv_pe);
        m = fmaxf(m, h);
        out[OFF_X + (bp*DD + d)*3 + 0] = dx;   /* x output = broadcast DIRS */
        out[OFF_X + (bp*DD + d)*3 + 1] = dy;
        out[OFF_X + (bp*DD + d)*3 + 2] = dz;
    }
    red[t] = m;
    __syncthreads();
    for (int s = 64; s > 0; s >>= 1) {
        if (t < s) red[t] = fmaxf(red[t], red[t+s]);
        __syncthreads();
    }
    if (t == 0) g_scale[bp] = fminf(fmaxf(red[0], 1e-10f), 10.0f);
}

/* ---------------- kernel 2: overlap (P x P per batch) ---------------------- */
__global__ void k_overlap(const float* __restrict__ smooth,
                          float* __restrict__ out)
{
    __shared__ float av[PP*VV*3];   /* 1536 */
    __shared__ float am[PP*3];
    __shared__ float H[PP*PP];
    int b = blockIdx.x, t = threadIdx.x;
    for (int idx = t; idx < PP*VV*3; idx += 256) av[idx] = g_lv[b*PP*VV*3 + idx];
    if (t < PP*3) am[t] = g_mean[b*PP*3 + t];
    __syncthreads();

    int i = t / PP, j = t % PP;
    float fx = am[3*j]   - am[3*i];
    float fy = am[3*j+1] - am[3*i+1];
    float fz = am[3*j+2] - am[3*i+2];
    float s2 = fminf(fmaxf(fx*fx + fy*fy + fz*fz, 1e-20f), 1e20f);
    float dn = sqrtf(s2);
    float dx, dy, dz;
    if (i == j) { dx = 1.f; dy = 0.f; dz = 0.f; }
    else { float inv = 1.0f/dn; dx = fx*inv; dy = fy*inv; dz = fz*inv; }
    float pe = smooth[b*PP + i], inv_pe = 1.0f/pe;
    H[t] = support_hout(av + i*VV*3, dx, dy, dz, pe, inv_pe);
    __syncthreads();
    float sep = dn - H[i*PP + j] - H[j*PP + i];
    float ov = fmaxf(-sep, 0.f) * ((i == j) ? 0.f : 1.f);
    out[OFF_OVERLAP + b*PP*PP + t] = ov;
}

/* -------- kernel 3: surf_points + normals (query = DIRS*scale + mean) ------ */
/* Normals feed the nf<0 threshold in k_surfd: use reference-matching rounding
   (separate mul/add, IEEE sqrt & div) to avoid sign flips on borderline nf.   */
__global__ void k_surf(const float* __restrict__ smooth,
                       float* __restrict__ out)
{
    __shared__ float sv[VV*3];
    __shared__ float smean[3];
    int bp = blockIdx.x, t = threadIdx.x;
    if (t < VV*3) sv[t] = g_lv[bp*VV*3 + t];
    if (t < 3)    smean[t] = g_mean[bp*3 + t];
    __syncthreads();
    float pe = smooth[bp], inv_pe = 1.0f/pe;
    float scale = g_scale[bp];

    for (int d = t; d < DD; d += blockDim.x) {
        /* pts = DIRS*scale + mean; local = pts - mean (round like reference: no fma) */
        float mx = __fmul_rn(g_dirs[3*d],   scale);
        float my = __fmul_rn(g_dirs[3*d+1], scale);
        float mz = __fmul_rn(g_dirs[3*d+2], scale);
        float qx = __fadd_rn(mx, smean[0]);
        float qy = __fadd_rn(my, smean[1]);
        float qz = __fadd_rn(mz, smean[2]);
        float lx = __fadd_rn(qx, -smean[0]);
        float ly = __fadd_rn(qy, -smean[1]);
        float lz = __fadd_rn(qz, -smean[2]);
        float s2 = fminf(fmaxf(__fmaf_rn(lz, lz, __fmaf_rn(ly, ly, __fmul_rn(lx, lx))), 1e-40f), 1e40f);
        float nrm = __fsqrt_rn(s2);
        float dx = __fdiv_rn(lx, nrm), dy = __fdiv_rn(ly, nrm), dz = __fdiv_rn(lz, nrm);
        g_norm[(bp*DD + d)*3 + 0] = dx;
        g_norm[(bp*DD + d)*3 + 1] = dy;
        g_norm[(bp*DD + d)*3 + 2] = dz;

        /* full _spt with surf */
        float z[VV]; float zmax = -1e30f;
#pragma unroll
        for (int v = 0; v < VV; v++) {
            float zz = fmaf(sv[3*v+2], dz, fmaf(sv[3*v+1], dy, sv[3*v]*dx));
            z[v] = zz; zmax = fmaxf(zmax, zz);
        }
        float maxz = fminf(fmaxf(zmax, 1e-30f), 1e30f);
        float k = frcp(maxz);
        float sum = 0.f;
#pragma unroll
        for (int v = 0; v < VV; v++) {
            float tt = fmaxf(z[v], 0.f) * k;
            sum += fex2(pe * flg2(tt));
        }
        float h = fex2(inv_pe * flg2(sum));
        float s = fminf(fmaxf(h, 1e-30f), 1e30f);
        float inv_s = frcp(s);
        float pem1 = pe - 1.0f;
        float ax = 0.f, ay = 0.f, az = 0.f;
#pragma unroll
        for (int v = 0; v < VV; v++) {
            float tt = fmaxf(fmaxf(z[v], 0.f)*k, 1e-30f);   /* zmk clip */
            float w = fex2(pem1 * flg2(tt * inv_s));
            w = fminf(fmaxf(w, 1e-30f), 1e30f);             /* dhdz clip */
            ax = fmaf(w, sv[3*v],   ax);
            ay = fmaf(w, sv[3*v+1], ay);
            az = fmaf(w, sv[3*v+2], az);
        }
        out[OFF_SURFP + (bp*DD + d)*3 + 0] = ax + smean[0];
        out[OFF_SURFP + (bp*DD + d)*3 + 1] = ay + smean[1];
        out[OFF_SURFP + (bp*DD + d)*3 + 2] = az + smean[2];
    }
}

/* ------ kernel 4: distance over all three query sets in one launch --------- */
/* grid.x = 128 blocks of 256 threads: [0,64) pc, [64,96) ns, [96,128) out.    */
__global__ void k_dist_all(const float* __restrict__ pc,
                           const float* __restrict__ ns,
                           const float* __restrict__ od,
                           const float* __restrict__ smooth,
                           float* __restrict__ out)
{
    __shared__ float sv[VV*3];
    __shared__ float smean[3];
    int bp = blockIdx.y, b = bp / PP;
    int t = threadIdx.x;
    if (t < VV*3) sv[t] = g_lv[bp*VV*3 + t];
    if (t < 3)    smean[t] = g_mean[bp*3 + t];
    __syncthreads();

    const float* pts;
    float* outp;
    int n, N;
    int bx = blockIdx.x;
    if (bx < 64)      { pts = pc; outp = out + OFF_DIST; N = N_PC; n =  bx      *256 + t; }
    else if (bx < 96) { pts = ns; outp = out + OFF_NS;   N = N_NS; n = (bx - 64)*256 + t; }
    else              { pts = od; outp = out + OFF_OUTD; N = N_OD; n = (bx - 96)*256 + t; }

    float pe = smooth[bp], inv_pe = 1.0f/pe;
    float3 q = *(const float3*)(pts + (size_t)(b*N + n)*3);
    float lx = q.x - smean[0], ly = q.y - smean[1], lz = q.z - smean[2];
    float s2 = fminf(fmaxf(lx*lx + ly*ly + lz*lz, 1e-40f), 1e40f);
    float inv = frsq(s2);
    float nrm = s2 * inv;     /* = sqrt(s2) */
    float h = support_hout(sv, lx*inv, ly*inv, lz*inv, pe, inv_pe);
    outp[bp*N + n] = nrm - h;
}

/* --------- kernel 5: surf_distance with normal filter + diagonal ----------- */
__global__ void k_surfd(const float* __restrict__ smooth,
                        float* __restrict__ out)
{
    __shared__ float sv[VV*3];
    __shared__ float am[PP*3];
    int bp = blockIdx.y, b = bp / PP, i = bp % PP;
    int t = threadIdx.x;
    if (t < VV*3) sv[t] = g_lv[bp*VV*3 + t];
    if (t < PP*3) am[t] = g_mean[b*PP*3 + t];
    __syncthreads();
    int m = blockIdx.x*blockDim.x + t;
    if (m >= PD) return;
    int j = m / DD, d = m % DD;
    float res;
    if (j == i) {
        res = 100.0f;                       /* diagonal override */
    } else {
        float nx = g_norm[(bp*DD + d)*3 + 0];
        float ny = g_norm[(bp*DD + d)*3 + 1];
        float nz = g_norm[(bp*DD + d)*3 + 2];
        float tx = __fadd_rn(am[3*j],   -am[3*i]);
        float ty = __fadd_rn(am[3*j+1], -am[3*i+1]);
        float tz = __fadd_rn(am[3*j+2], -am[3*i+2]);
        float nf = __fmaf_rn(tz, nz, __fmaf_rn(ty, ny, __fmul_rn(tx, nx)));
        if (nf < 0.f) {
            res = 100.0f;                   /* normal filter */
        } else {
            float pe = smooth[bp], inv_pe = 1.0f/pe;
            float3 q = *(const float3*)(out + OFF_SURFP + (size_t)(b*PD + m)*3);
            float lx = q.x - am[3*i], ly = q.y - am[3*i+1], lz = q.z - am[3*i+2];
            float s2 = fminf(fmaxf(lx*lx + ly*ly + lz*lz, 1e-40f), 1e40f);
            float inv = frsq(s2);
            float nrm = s2 * inv;
            float h = support_hout(sv, lx*inv, ly*inv, lz*inv, pe, inv_pe);
            res = nrm - h;
        }
    }
    out[OFF_SURFD + bp*PD + m] = res;
}

extern "C" void kernel_launch(void* const* d_in, const int* in_sizes, int n_in,
                              void* d_out, int out_size)
{
    const float* verts  = (const float*)d_in[0];   /* (B,P,V,3)  */
    const float* smooth = (const float*)d_in[1];   /* (B,P)      */
    const float* pc     = (const float*)d_in[2];   /* (B,NPC,3)  */
    const float* ns     = (const float*)d_in[3];   /* (B,NNS,3)  */
    const float* od     = (const float*)d_in[4];   /* (B,NOUT,3) */
    float* out = (float*)d_out;

    k_dirs<<<1, DD>>>();
    k_prep<<<BB*PP, 128>>>(verts, smooth, out);
    k_overlap<<<BB, 256>>>(smooth, out);
    k_surf<<<BB*PP, 128>>>(smooth, out);
    k_dist_all<<<dim3(128, BB*PP), 256>>>(pc, ns, od, smooth, out);
    k_surfd<<<dim3((PD + 255)/256, BB*PP), 256>>>(smooth, out);
}

// round 17
// speedup vs baseline: 1.0063x; 1.0063x over previous
#include <cuda_runtime.h>
#include <math.h>

#define BB 8
#define PP 16
#define VV 32
#define DD 686
#define N_PC 16384
#define N_NS 8192
#define N_OD 8192
#define PD (PP*DD)          /* 10976 */

/* Output layout: tuple members flattened & concatenated in order */
#define OFF_OVERLAP 0
#define OFF_DIST    2048
#define OFF_X       2099200
#define OFF_SURFD   2362624
#define OFF_SURFP   3767552
#define OFF_NS      4030976
#define OFF_OUTD    5079552

__device__ float g_dirs[DD*3];
__device__ float g_lv[BB*PP*VV*3];
__device__ float g_mean[BB*PP*3];
__device__ float g_scale[BB*PP];
__device__ unsigned int g_scale_raw[BB*PP];
__device__ float g_norm[BB*PP*DD*3];

__device__ __forceinline__ float fex2(float x){ float y; asm("ex2.approx.f32 %0, %1;" : "=f"(y) : "f"(x)); return y; }
__device__ __forceinline__ float flg2(float x){ float y; asm("lg2.approx.f32 %0, %1;" : "=f"(y) : "f"(x)); return y; }
__device__ __forceinline__ float frcp(float x){ float y; asm("rcp.approx.f32 %0, %1;" : "=f"(y) : "f"(x)); return y; }
__device__ __forceinline__ float frsq(float x){ float y; asm("rsqrt.approx.f32 %0, %1;" : "=f"(y) : "f"(x)); return y; }

/* h_out = (sum_v clip(max(z_v,0)/maxz)^pe)^(1/pe) * maxz */
__device__ __forceinline__ float support_hout(const float* __restrict__ sv,
                                              float dx, float dy, float dz,
                                              float pe, float inv_pe)
{
    float z[VV];
    float zmax = -1e30f;
#pragma unroll
    for (int v = 0; v < VV; v++) {
        float zz = fmaf(sv[3*v+2], dz, fmaf(sv[3*v+1], dy, sv[3*v]*dx));
        z[v] = zz;
        zmax = fmaxf(zmax, zz);
    }
    float maxz = fminf(fmaxf(zmax, 1e-30f), 1e30f);
    float k = frcp(maxz);
    float sum = 0.f;
#pragma unroll
    for (int v = 0; v < VV; v++) {
        float t = fmaxf(z[v], 0.f) * k;       /* lg2(0) = -inf -> ex2 = 0: exact zero contribution */
        sum += fex2(pe * flg2(t));
    }
    float h = fex2(inv_pe * flg2(sum));
    return h * maxz;
}

/* Dual-query support eval: two independent chains interleaved for ILP.
   Bit-identical per point to support_hout (same ops, same order).            */
__device__ __forceinline__ void support_hout2(const float* __restrict__ sv,
                                              float dx0, float dy0, float dz0,
                                              float dx1, float dy1, float dz1,
                                              float pe, float inv_pe,
                                              float& h0, float& h1)
{
    float z0[VV], z1[VV];
    float zmax0 = -1e30f, zmax1 = -1e30f;
#pragma unroll
    for (int v = 0; v < VV; v++) {
        float vx = sv[3*v], vy = sv[3*v+1], vz = sv[3*v+2];
        float a = fmaf(vz, dz0, fmaf(vy, dy0, vx*dx0));
        float b = fmaf(vz, dz1, fmaf(vy, dy1, vx*dx1));
        z0[v] = a; zmax0 = fmaxf(zmax0, a);
        z1[v] = b; zmax1 = fmaxf(zmax1, b);
    }
    float maxz0 = fminf(fmaxf(zmax0, 1e-30f), 1e30f);
    float maxz1 = fminf(fmaxf(zmax1, 1e-30f), 1e30f);
    float k0 = frcp(maxz0), k1 = frcp(maxz1);
    float sum0 = 0.f, sum1 = 0.f;
#pragma unroll
    for (int v = 0; v < VV; v++) {
        float t0 = fmaxf(z0[v], 0.f) * k0;
        float t1 = fmaxf(z1[v], 0.f) * k1;
        sum0 += fex2(pe * flg2(t0));
        sum1 += fex2(pe * flg2(t1));
    }
    h0 = fex2(inv_pe * flg2(sum0)) * maxz0;
    h1 = fex2(inv_pe * flg2(sum1)) * maxz1;
}

/* ---------------- kernel 0: directions (match numpy float64 path) ---------- */
__global__ void k_dirs()
{
    int t = threadIdx.x;
    if (t >= DD) return;
    const double PI = 3.14159265358979323846;
    int i, j;
    if (t < 684) { i = 1 + t/38; j = t % 38; }
    else if (t == 684) { i = 0;  j = 0; }
    else               { i = 19; j = 0; }
    double th1 = (i == 19) ? (PI*0.5) : (-PI*0.5 + (PI/19.0)*(double)i);
    double th2 = -PI + (PI/19.0)*(double)j;
    double c1 = cos(th1), s1 = sin(th1), c2 = cos(th2), s2 = sin(th2);
    g_dirs[t*3+0] = (float)(c1*c2);
    g_dirs[t*3+1] = (float)(c1*s2);
    g_dirs[t*3+2] = (float)(s1);
}

/* -------- kernel 1a: mean + local verts + zero scale accumulator ----------- */
__global__ void k_mean(const float* __restrict__ verts)
{
    __shared__ float sv[VV*3];
    __shared__ float smean[3];
    int bp = blockIdx.x, t = threadIdx.x;
    if (t < VV*3) sv[t] = verts[bp*VV*3 + t];
    __syncthreads();
    if (t < 3) {
        float s = 0.f;
        for (int v = 0; v < VV; v++) s += sv[3*v + t];
        smean[t] = s * (1.0f/32.0f);
        g_mean[bp*3 + t] = smean[t];
    }
    __syncthreads();
    if (t < VV*3) g_lv[bp*VV*3 + t] = sv[t] - smean[t % 3];
    if (t == 0) g_scale_raw[bp] = 0u;   /* h >= 0, float-as-uint max is valid */
}

/* -------- kernel 1b: support over DIRS -> x output + scale atomicMax ------- */
__global__ void __launch_bounds__(128, 3)
k_prep2(const float* __restrict__ smooth, float* __restrict__ out)
{
    __shared__ float sv[VV*3];
    int bp = blockIdx.x, t = threadIdx.x;
    if (t < VV*3) sv[t] = g_lv[bp*VV*3 + t];
    __syncthreads();
    int d = blockIdx.y*128 + t;
    if (d >= DD) return;
    float pe = smooth[bp], inv_pe = 1.0f/pe;
    float dx = g_dirs[3*d], dy = g_dirs[3*d+1], dz = g_dirs[3*d+2];
    float h = support_hout(sv, dx, dy, dz, pe, inv_pe);
    out[OFF_X + (bp*DD + d)*3 + 0] = dx;   /* x output = broadcast DIRS */
    out[OFF_X + (bp*DD + d)*3 + 1] = dy;
    out[OFF_X + (bp*DD + d)*3 + 2] = dz;
    /* warp-level pre-reduction, then one atomic per warp */
    float m = h;
#pragma unroll
    for (int o = 16; o > 0; o >>= 1)
        m = fmaxf(m, __shfl_down_sync(0xFFFFFFFFu, m, o));
    if ((t & 31) == 0) atomicMax(&g_scale_raw[bp], __float_as_uint(m));
}

/* -------- kernel 1c: clip max support into g_scale ------------------------- */
__global__ void k_scale()
{
    int bp = threadIdx.x;
    float m = __uint_as_float(g_scale_raw[bp]);
    g_scale[bp] = fminf(fmaxf(m, 1e-10f), 10.0f);
}

/* ---------------- kernel 2: overlap (P x P per batch) ---------------------- */
__global__ void k_overlap(const float* __restrict__ smooth,
                          float* __restrict__ out)
{
    __shared__ float av[PP*VV*3];   /* 1536 */
    __shared__ float am[PP*3];
    __shared__ float H[PP*PP];
    int b = blockIdx.x, t = threadIdx.x;
    for (int idx = t; idx < PP*VV*3; idx += 256) av[idx] = g_lv[b*PP*VV*3 + idx];
    if (t < PP*3) am[t] = g_mean[b*PP*3 + t];
    __syncthreads();

    int i = t / PP, j = t % PP;
    float fx = am[3*j]   - am[3*i];
    float fy = am[3*j+1] - am[3*i+1];
    float fz = am[3*j+2] - am[3*i+2];
    float s2 = fminf(fmaxf(fx*fx + fy*fy + fz*fz, 1e-20f), 1e20f);
    float dn = sqrtf(s2);
    float dx, dy, dz;
    if (i == j) { dx = 1.f; dy = 0.f; dz = 0.f; }
    else { float inv = 1.0f/dn; dx = fx*inv; dy = fy*inv; dz = fz*inv; }
    float pe = smooth[b*PP + i], inv_pe = 1.0f/pe;
    H[t] = support_hout(av + i*VV*3, dx, dy, dz, pe, inv_pe);
    __syncthreads();
    float sep = dn - H[i*PP + j] - H[j*PP + i];
    float ov = fmaxf(-sep, 0.f) * ((i == j) ? 0.f : 1.f);
    out[OFF_OVERLAP + b*PP*PP + t] = ov;
}

/* -------- kernel 3: surf_points + normals (query = DIRS*scale + mean) ------ */
/* Normals feed the nf<0 threshold in k_surfd: use reference-matching rounding
   (separate mul/add, IEEE sqrt & div) to avoid sign flips on borderline nf.
   launch_bounds(128,2): highest-reg kernel, avoid any spill risk.            */
__global__ void __launch_bounds__(128, 2)
k_surf(const float* __restrict__ smooth, float* __restrict__ out)
{
    __shared__ float sv[VV*3];
    __shared__ float smean[3];
    int bp = blockIdx.x, t = threadIdx.x;
    if (t < VV*3) sv[t] = g_lv[bp*VV*3 + t];
    if (t < 3)    smean[t] = g_mean[bp*3 + t];
    __syncthreads();
    int d = blockIdx.y*128 + t;
    if (d >= DD) return;
    float pe = smooth[bp], inv_pe = 1.0f/pe;
    float scale = g_scale[bp];

    /* pts = DIRS*scale + mean; local = pts - mean (round like reference: no fma) */
    float mx = __fmul_rn(g_dirs[3*d],   scale);
    float my = __fmul_rn(g_dirs[3*d+1], scale);
    float mz = __fmul_rn(g_dirs[3*d+2], scale);
    float qx = __fadd_rn(mx, smean[0]);
    float qy = __fadd_rn(my, smean[1]);
    float qz = __fadd_rn(mz, smean[2]);
    float lx = __fadd_rn(qx, -smean[0]);
    float ly = __fadd_rn(qy, -smean[1]);
    float lz = __fadd_rn(qz, -smean[2]);
    float s2 = fminf(fmaxf(__fmaf_rn(lz, lz, __fmaf_rn(ly, ly, __fmul_rn(lx, lx))), 1e-40f), 1e40f);
    float nrm = __fsqrt_rn(s2);
    float dx = __fdiv_rn(lx, nrm), dy = __fdiv_rn(ly, nrm), dz = __fdiv_rn(lz, nrm);
    g_norm[(bp*DD + d)*3 + 0] = dx;
    g_norm[(bp*DD + d)*3 + 1] = dy;
    g_norm[(bp*DD + d)*3 + 2] = dz;

    /* full _spt with surf */
    float z[VV]; float zmax = -1e30f;
#pragma unroll
    for (int v = 0; v < VV; v++) {
        float zz = fmaf(sv[3*v+2], dz, fmaf(sv[3*v+1], dy, sv[3*v]*dx));
        z[v] = zz; zmax = fmaxf(zmax, zz);
    }
    float maxz = fminf(fmaxf(zmax, 1e-30f), 1e30f);
    float k = frcp(maxz);
    float sum = 0.f;
#pragma unroll
    for (int v = 0; v < VV; v++) {
        float tt = fmaxf(z[v], 0.f) * k;
        sum += fex2(pe * flg2(tt));
    }
    float h = fex2(inv_pe * flg2(sum));
    float s = fminf(fmaxf(h, 1e-30f), 1e30f);
    float inv_s = frcp(s);
    float pem1 = pe - 1.0f;
    float ax = 0.f, ay = 0.f, az = 0.f;
#pragma unroll
    for (int v = 0; v < VV; v++) {
        float tt = fmaxf(fmaxf(z[v], 0.f)*k, 1e-30f);   /* zmk clip */
        float w = fex2(pem1 * flg2(tt * inv_s));
        w = fminf(fmaxf(w, 1e-30f), 1e30f);             /* dhdz clip */
        ax = fmaf(w, sv[3*v],   ax);
        ay = fmaf(w, sv[3*v+1], ay);
        az = fmaf(w, sv[3*v+2], az);
    }
    out[OFF_SURFP + (bp*DD + d)*3 + 0] = ax + smean[0];
    out[OFF_SURFP + (bp*DD + d)*3 + 1] = ay + smean[1];
    out[OFF_SURFP + (bp*DD + d)*3 + 2] = az + smean[2];
}

/* ------ kernel 4: distance, 2 query points per thread (ILP x2) ------------- */
/* grid.x = 128 blocks of 128 threads, each thread does 2 consecutive points:
   [0,64) pc, [64,96) ns, [96,128) out.                                       */
__global__ void __launch_bounds__(128, 2)
k_dist_all(const float* __restrict__ pc,
           const float* __restrict__ ns,
           const float* __restrict__ od,
           const float* __restrict__ smooth,
           float* __restrict__ out)
{
    __shared__ float sv[VV*3];
    __shared__ float smean[3];
    int bp = blockIdx.y, b = bp / PP;
    int t = threadIdx.x;
    if (t < VV*3) sv[t] = g_lv[bp*VV*3 + t];
    if (t < 3)    smean[t] = g_mean[bp*3 + t];
    __syncthreads();

    const float* pts;
    float* outp;
    int n, N;
    int bx = blockIdx.x;
    if (bx < 64)      { pts = pc; outp = out + OFF_DIST; N = N_PC; n = ( bx      *128 + t)*2; }
    else if (bx < 96) { pts = ns; outp = out + OFF_NS;   N = N_NS; n = ((bx - 64)*128 + t)*2; }
    else              { pts = od; outp = out + OFF_OUTD; N = N_OD; n = ((bx - 96)*128 + t)*2; }

    float pe = smooth[bp], inv_pe = 1.0f/pe;
    const float* q = pts + (size_t)(b*N + n)*3;
    float q0x = q[0], q0y = q[1], q0z = q[2];
    float q1x = q[3], q1y = q[4], q1z = q[5];

    float l0x = q0x - smean[0], l0y = q0y - smean[1], l0z = q0z - smean[2];
    float l1x = q1x - smean[0], l1y = q1y - smean[1], l1z = q1z - smean[2];
    float s20 = fminf(fmaxf(l0x*l0x + l0y*l0y + l0z*l0z, 1e-40f), 1e40f);
    float s21 = fminf(fmaxf(l1x*l1x + l1y*l1y + l1z*l1z, 1e-40f), 1e40f);
    float iv0 = frsq(s20), iv1 = frsq(s21);
    float nr0 = s20 * iv0, nr1 = s21 * iv1;
    float h0, h1;
    support_hout2(sv, l0x*iv0, l0y*iv0, l0z*iv0,
                      l1x*iv1, l1y*iv1, l1z*iv1, pe, inv_pe, h0, h1);
    outp[bp*N + n]     = nr0 - h0;
    outp[bp*N + n + 1] = nr1 - h1;
}

/* --------- kernel 5: surf_distance with normal filter + diagonal ----------- */
__global__ void __launch_bounds__(128, 3)
k_surfd(const float* __restrict__ smooth, float* __restrict__ out)
{
    __shared__ float sv[VV*3];
    __shared__ float am[PP*3];
    int bp = blockIdx.y, b = bp / PP, i = bp % PP;
    int t = threadIdx.x;
    if (t < VV*3) sv[t] = g_lv[bp*VV*3 + t];
    if (t < PP*3) am[t] = g_mean[b*PP*3 + t];
    __syncthreads();
    int m = blockIdx.x*128 + t;
    if (m >= PD) return;
    int j = m / DD, d = m % DD;
    float res;
    if (j == i) {
        res = 100.0f;                       /* diagonal override */
    } else {
        float nx = g_norm[(bp*DD + d)*3 + 0];
        float ny = g_norm[(bp*DD + d)*3 + 1];
        float nz = g_norm[(bp*DD + d)*3 + 2];
        float tx = __fadd_rn(am[3*j],   -am[3*i]);
        float ty = __fadd_rn(am[3*j+1], -am[3*i+1]);
        float tz = __fadd_rn(am[3*j+2], -am[3*i+2]);
        float nf = __fmaf_rn(tz, nz, __fmaf_rn(ty, ny, __fmul_rn(tx, nx)));
        if (nf < 0.f) {
            res = 100.0f;                   /* normal filter */
        } else {
            float pe = smooth[bp], inv_pe = 1.0f/pe;
            float3 q = *(const float3*)(out + OFF_SURFP + (size_t)(b*PD + m)*3);
            float lx = q.x - am[3*i], ly = q.y - am[3*i+1], lz = q.z - am[3*i+2];
            float s2 = fminf(fmaxf(lx*lx + ly*ly + lz*lz, 1e-40f), 1e40f);
            float inv = frsq(s2);
            float nrm = s2 * inv;
            float h = support_hout(sv, lx*inv, ly*inv, lz*inv, pe, inv_pe);
            res = nrm - h;
        }
    }
    out[OFF_SURFD + bp*PD + m] = res;
}

extern "C" void kernel_launch(void* const* d_in, const int* in_sizes, int n_in,
                              void* d_out, int out_size)
{
    const float* verts  = (const float*)d_in[0];   /* (B,P,V,3)  */
    const float* smooth = (const float*)d_in[1];   /* (B,P)      */
    const float* pc     = (const float*)d_in[2];   /* (B,NPC,3)  */
    const float* ns     = (const float*)d_in[3];   /* (B,NNS,3)  */
    const float* od     = (const float*)d_in[4];   /* (B,NOUT,3) */
    float* out = (float*)d_out;

    k_dirs<<<1, DD>>>();
    k_mean<<<BB*PP, 128>>>(verts);
    k_prep2<<<dim3(BB*PP, 6), 128>>>(smooth, out);
    k_scale<<<1, BB*PP>>>();
    k_overlap<<<BB, 256>>>(smooth, out);
    k_surf<<<dim3(BB*PP, 6), 128>>>(smooth, out);
    k_dist_all<<<dim3(128, BB*PP), 128>>>(pc, ns, od, smooth, out);
    k_surfd<<<dim3((PD + 127)/128, BB*PP), 128>>>(smooth, out);
}